// round 5
// baseline (speedup 1.0000x reference)
#include <cuda_runtime.h>
#include <math.h>

// Problem constants (fixed by setup_inputs)
#define BB 32
#define EE 256
#define HH 512
#define VV 32000
#define TT 128

#define NBLK 125          // 125 blocks, 1 per SM, persistent
#define NTHR 256
#define VP   (VV/2)       // 16000 v-pairs
#define XS 260            // phase A x smem row stride (floats)
#define HSA 516           // phase A h smem row stride (floats)
// phase B: hdup [512][32] ull = 131072 B, then wbuf 64 ull = 512 B
#define SMEM_BYTES (131072 + 1024)

typedef unsigned long long ull;

// ---------------- device globals (no allocation allowed) ----------------
// Transposed, v-pair-packed fc_w: ull at [k2][vp][s] (k = 2*k2+s) holds
// (w[k][2vp], w[k][2vp+1]).  256*16000*2 ull = 65.5 MB (L2-resident).
__device__ ull   g_fcwT2[(size_t)(HH / 2) * VP * 2];
__device__ float g_h[2][BB * HH];       // double-buffered hidden state (plain)
__device__ ull   g_hdup[HH * BB];       // h duplicated: [k][b] = (h[b][k], h[b][k])
__device__ ull   g_amax[2][BB];         // packed (value,idx) argmax per batch
__device__ unsigned g_barcnt;
__device__ unsigned g_barflag;

// ---------------- helpers ----------------
__device__ __forceinline__ void ffma2(ull& d, ull a, ull b) {
    asm("fma.rn.f32x2 %0, %1, %2, %0;" : "+l"(d) : "l"(a), "l"(b));
}
__device__ __forceinline__ ull dl(double d) { return __double_as_longlong(d); }
__device__ __forceinline__ float lof(ull a) { return __uint_as_float((unsigned)a); }
__device__ __forceinline__ float hif(ull a) { return __uint_as_float((unsigned)(a >> 32)); }
__device__ __forceinline__ float red2(ull a) { return lof(a) + hif(a); }
__device__ __forceinline__ ull packcand(float val, int v) {
    unsigned u = __float_as_uint(val);
    u = (u & 0x80000000u) ? ~u : (u | 0x80000000u);   // order-preserving map
    return ((ull)u << 32) | (ull)(0xFFFFFFFFu - (unsigned)v);  // ties -> smallest idx
}
__device__ __forceinline__ void stcs2(float* p, float a, float b) {
    asm volatile("st.global.cs.v2.f32 [%0], {%1, %2};" :: "l"(p), "f"(a), "f"(b)
                 : "memory");
}

// sense-counting grid barrier (125 blocks <= 148 SMs -> all co-resident)
__device__ __forceinline__ void grid_sync(unsigned& gen) {
    gen++;
    __threadfence();
    __syncthreads();
    if (threadIdx.x == 0) {
        unsigned prev = atomicAdd(&g_barcnt, 1);
        if (prev == NBLK - 1) {
            atomicExch(&g_barcnt, 0);
            __threadfence();
            *(volatile unsigned*)&g_barflag = gen;
        } else {
            while (*(volatile unsigned*)&g_barflag < gen) { }
        }
    }
    __syncthreads();
}

// ---------------- init (runs each replay; deterministic) ----------------
__global__ void init_kernel(const float* __restrict__ ctx) {
    int i = blockIdx.x * blockDim.x + threadIdx.x;
    if (i < BB * HH) g_h[0][i] = ctx[i];
    if (i == 0) { g_barcnt = 0; g_barflag = 0; }
}

// ---------------- fc_w transpose: [V][H] -> k-major v-pair-packed ----------------
// grid = VV blocks (one v row each), 256 threads (one k2 each). Reads coalesced.
__global__ void transpose_kernel(const float* __restrict__ fc_w) {
    int v = blockIdx.x;          // 0..31999
    int k2 = threadIdx.x;        // 0..255
    float2 w = *(const float2*)(fc_w + (size_t)v * HH + 2 * k2);  // k=2k2, 2k2+1
    int vp = v >> 1, j = v & 1;
    float* o = (float*)g_fcwT2;
    size_t base = ((size_t)k2 * VP + vp) * 4 + j;
    o[base]     = w.x;   // s = 0
    o[base + 2] = w.y;   // s = 1
}

// ---------------- main persistent decoder ----------------
__global__ void __launch_bounds__(NTHR, 1)
decoder_kernel(const float* __restrict__ embed,
               const float* __restrict__ w_ih,
               const float* __restrict__ w_hh,
               const float* __restrict__ b_ih,
               const float* __restrict__ b_hh,
               const float* __restrict__ fc_b,
               float* __restrict__ out,
               float* __restrict__ pred) {
    extern __shared__ float smem[];
    const int tid  = threadIdx.x;
    const int gtid = blockIdx.x * NTHR + tid;
    unsigned gen = 0;
    __shared__ int tok_sh[BB];

    const bool doA = (blockIdx.x < (BB * HH) / NTHR);   // first 64 blocks run GRU

    // phase B thread mapping: thread owns 2 v-pairs (vp0, vp0+64) and 8 batches
    const int lvq = tid & 63;                  // 0..63
    const int bq  = tid >> 6;                  // 0..3
    const int vp0 = blockIdx.x * 128 + lvq;
    const int vp1 = vp0 + 64;
    const int b0  = bq * 8;
    const int wid = tid >> 5, lane = tid & 31;

    for (int t = 0; t < TT; ++t) {
        const float* hsrc = g_h[t & 1];
        float*       hdst = g_h[(t + 1) & 1];

        // ===================== Phase A: token decode + GRU cell =====================
        if (doA) {
            if (tid < BB) {
                int tk;
                if (t == 0) {
                    tk = 1;  // START_IDX
                } else {
                    ull p = *(volatile ull*)&g_amax[(t - 1) & 1][tid];
                    tk = (int)(0xFFFFFFFFu - (unsigned)(p & 0xFFFFFFFFull));
                }
                tok_sh[tid] = tk;
                if (blockIdx.x == 0) {
                    if (t > 0 && pred) pred[(size_t)tid * TT + (t - 1)] = (float)tk;
                    *(volatile ull*)&g_amax[t & 1][tid] = 0ull;   // reset this step's buf
                }
            }
            __syncthreads();

            float* xs  = smem;              // [BB][XS]
            float* hsA = smem + BB * XS;    // [BB][HSA]

            for (int i = tid; i < BB * (EE / 4); i += NTHR) {
                int b = i / (EE / 4), k = (i % (EE / 4)) * 4;
                float4 v = *(const float4*)(embed + (size_t)tok_sh[b] * EE + k);
                *(float4*)(xs + b * XS + k) = v;
            }
            for (int i = tid; i < BB * (HH / 4); i += NTHR) {
                int b = i / (HH / 4), k = (i % (HH / 4)) * 4;
                float4 v = __ldcg((const float4*)(hsrc + (size_t)b * HH + k));
                *(float4*)(hsA + b * HSA + k) = v;
            }
            __syncthreads();

            const int pair = gtid;       // < 16384
            const int b = pair & 31;     // lane = batch -> warp-uniform weight rows
            const int i = pair >> 5;

            ull a_ir = 0, a_iz = 0, a_in = 0;
            ull a_hr = 0, a_hz = 0, a_hn = 0;
            {
                const double2* wr = (const double2*)(w_ih + (size_t)i * EE);
                const double2* wz = wr + (size_t)HH * EE / 4;
                const double2* wn = wr + (size_t)2 * HH * EE / 4;
                const double2* xv = (const double2*)(xs + b * XS);
                #pragma unroll 4
                for (int k = 0; k < EE / 4; k++) {
                    double2 x2 = xv[k];
                    double2 r2 = __ldg(wr + k);
                    double2 z2 = __ldg(wz + k);
                    double2 n2 = __ldg(wn + k);
                    ffma2(a_ir, dl(r2.x), dl(x2.x)); ffma2(a_ir, dl(r2.y), dl(x2.y));
                    ffma2(a_iz, dl(z2.x), dl(x2.x)); ffma2(a_iz, dl(z2.y), dl(x2.y));
                    ffma2(a_in, dl(n2.x), dl(x2.x)); ffma2(a_in, dl(n2.y), dl(x2.y));
                }
            }
            {
                const double2* wr = (const double2*)(w_hh + (size_t)i * HH);
                const double2* wz = wr + (size_t)HH * HH / 4;
                const double2* wn = wr + (size_t)2 * HH * HH / 4;
                const double2* hv = (const double2*)(hsA + b * HSA);
                #pragma unroll 4
                for (int k = 0; k < HH / 4; k++) {
                    double2 h2 = hv[k];
                    double2 r2 = __ldg(wr + k);
                    double2 z2 = __ldg(wz + k);
                    double2 n2 = __ldg(wn + k);
                    ffma2(a_hr, dl(r2.x), dl(h2.x)); ffma2(a_hr, dl(r2.y), dl(h2.y));
                    ffma2(a_hz, dl(z2.x), dl(h2.x)); ffma2(a_hz, dl(z2.y), dl(h2.y));
                    ffma2(a_hn, dl(n2.x), dl(h2.x)); ffma2(a_hn, dl(n2.y), dl(h2.y));
                }
            }
            float ir  = red2(a_ir) + __ldg(b_ih + i);
            float iz  = red2(a_iz) + __ldg(b_ih + HH + i);
            float inn = red2(a_in) + __ldg(b_ih + 2 * HH + i);
            float hr  = red2(a_hr) + __ldg(b_hh + i);
            float hz  = red2(a_hz) + __ldg(b_hh + HH + i);
            float hn  = red2(a_hn) + __ldg(b_hh + 2 * HH + i);
            float r = 1.0f / (1.0f + expf(-(ir + hr)));
            float z = 1.0f / (1.0f + expf(-(iz + hz)));
            float n = tanhf(fmaf(r, hn, inn));
            float hold = hsA[b * HSA + i];
            float hnew = n + z * (hold - n);
            hdst[(size_t)b * HH + i] = hnew;

            // duplicated h for phase B: [k][b] ull = (h,h); coalesced across warp
            unsigned hb = __float_as_uint(hnew);
            g_hdup[i * BB + b] = ((ull)hb << 32) | (ull)hb;
        }

        grid_sync(gen);

        // ===================== Phase B: logits GEMM + argmax =====================
        {
            ull* hdup_s = (ull*)smem;            // [HH][BB]  = 16384 ull (128 KB)
            ull* wbuf   = hdup_s + HH * BB;      // 64 ull

            // stage duplicated h (coalesced, L1-bypass: written by other SMs)
            {
                const double2* src = (const double2*)g_hdup;
                double2* dst = (double2*)hdup_s;
                #pragma unroll 4
                for (int i = tid; i < HH * BB / 2; i += NTHR)
                    dst[i] = __ldcg(src + i);
            }
            __syncthreads();

            // acc[vpi*8 + bi]: lanes = logits (2vp, 2vp+1) for batch b0+bi
            ull acc[16];
            #pragma unroll
            for (int j = 0; j < 16; ++j) acc[j] = 0ull;

            const double2* w0p = (const double2*)g_fcwT2 + vp0;
            const double2* w1p = (const double2*)g_fcwT2 + vp1;
            const double2* hs  = (const double2*)(hdup_s + b0);  // stride BB/2 per k

            // software pipeline depth 2 on w
            double2 wa0 = __ldcg(w0p), wa1 = __ldcg(w1p);
            w0p += VP; w1p += VP;
            double2 wb0 = __ldcg(w0p), wb1 = __ldcg(w1p);
            w0p += VP; w1p += VP;

            #pragma unroll 2
            for (int k2 = 0; k2 < HH / 2; ++k2) {
                const double2 cw0 = wa0, cw1 = wa1;
                wa0 = wb0; wa1 = wb1;
                if (k2 < HH / 2 - 2) {
                    wb0 = __ldcg(w0p); wb1 = __ldcg(w1p);
                    w0p += VP; w1p += VP;
                }
                // k = 2*k2 (s=0)
                {
                    const double2* h = hs + (size_t)(2 * k2) * (BB / 2);
                    const ull we0 = dl(cw0.x), we1 = dl(cw1.x);
                    #pragma unroll
                    for (int j = 0; j < 4; ++j) {
                        double2 hh = h[j];                   // broadcast LDS.128
                        ffma2(acc[2 * j],         we0, dl(hh.x));
                        ffma2(acc[2 * j + 1],     we0, dl(hh.y));
                        ffma2(acc[8 + 2 * j],     we1, dl(hh.x));
                        ffma2(acc[8 + 2 * j + 1], we1, dl(hh.y));
                    }
                }
                // k = 2*k2+1 (s=1)
                {
                    const double2* h = hs + (size_t)(2 * k2 + 1) * (BB / 2);
                    const ull wo0 = dl(cw0.y), wo1 = dl(cw1.y);
                    #pragma unroll
                    for (int j = 0; j < 4; ++j) {
                        double2 hh = h[j];
                        ffma2(acc[2 * j],         wo0, dl(hh.x));
                        ffma2(acc[2 * j + 1],     wo0, dl(hh.y));
                        ffma2(acc[8 + 2 * j],     wo1, dl(hh.x));
                        ffma2(acc[8 + 2 * j + 1], wo1, dl(hh.y));
                    }
                }
            }

            // epilogue: bias, streaming store, argmax candidates
            const int vA = 2 * vp0, vB = 2 * vp1;
            const float biasA0 = __ldg(fc_b + vA), biasA1 = __ldg(fc_b + vA + 1);
            const float biasB0 = __ldg(fc_b + vB), biasB1 = __ldg(fc_b + vB + 1);

            #pragma unroll
            for (int bi = 0; bi < 8; ++bi) {
                const int b = b0 + bi;
                float fa0 = lof(acc[bi])     + biasA0;
                float fa1 = hif(acc[bi])     + biasA1;
                float fb0 = lof(acc[8 + bi]) + biasB0;
                float fb1 = hif(acc[8 + bi]) + biasB1;

                float* op = out + ((size_t)b * TT + t) * VV;
                stcs2(op + vA, fa0, fa1);
                stcs2(op + vB, fb0, fb1);

                ull c = packcand(fa0, vA);
                { ull q = packcand(fa1, vA + 1); if (q > c) c = q; }
                { ull q = packcand(fb0, vB);     if (q > c) c = q; }
                { ull q = packcand(fb1, vB + 1); if (q > c) c = q; }
                #pragma unroll
                for (int off = 16; off; off >>= 1) {
                    ull q = __shfl_xor_sync(0xffffffffu, c, off);
                    if (q > c) c = q;
                }
                if (lane == 0) wbuf[wid * 8 + bi] = c;
            }
            __syncthreads();
            if (tid < BB) {
                const int bq2 = tid >> 3, bl = tid & 7;
                ull best = wbuf[(2 * bq2) * 8 + bl];
                ull q    = wbuf[(2 * bq2 + 1) * 8 + bl];
                if (q > best) best = q;
                atomicMax(&g_amax[t & 1][tid], best);
            }
        }

        grid_sync(gen);
    }

    // final step's predictions
    if (blockIdx.x == 0 && tid < BB && pred) {
        ull p = *(volatile ull*)&g_amax[(TT - 1) & 1][tid];
        pred[(size_t)tid * TT + (TT - 1)] =
            (float)(0xFFFFFFFFu - (unsigned)(p & 0xFFFFFFFFull));
    }
}

// ---------------- host launch ----------------
extern "C" void kernel_launch(void* const* d_in, const int* in_sizes, int n_in,
                              void* d_out, int out_size) {
    (void)in_sizes; (void)n_in;
    const float* ctx   = (const float*)d_in[0];
    const float* embed = (const float*)d_in[1];
    const float* w_ih  = (const float*)d_in[2];
    const float* w_hh  = (const float*)d_in[3];
    const float* b_ih  = (const float*)d_in[4];
    const float* b_hh  = (const float*)d_in[5];
    const float* fc_w  = (const float*)d_in[6];
    const float* fc_b  = (const float*)d_in[7];

    float* out = (float*)d_out;
    const long long logits_elems = (long long)BB * TT * VV;
    float* pred = ((long long)out_size >= logits_elems + (long long)BB * TT)
                      ? out + logits_elems : nullptr;

    cudaFuncSetAttribute(decoder_kernel,
                         cudaFuncAttributeMaxDynamicSharedMemorySize, SMEM_BYTES);

    init_kernel<<<(BB * HH + 255) / 256, 256>>>(ctx);
    transpose_kernel<<<VV, 256>>>(fc_w);
    decoder_kernel<<<NBLK, NTHR, SMEM_BYTES>>>(embed, w_ih, w_hh, b_ih, b_hh,
                                               fc_b, out, pred);
}